// round 5
// baseline (speedup 1.0000x reference)
#include <cuda_runtime.h>
#include <cstdint>

#define N 8400
#define WORDS 132          // ceil(8400/64)
#define SCORE_THR 0.5f
#define IOU_THR 0.5f
#define GRID 136           // <= 148 SMs: all blocks co-resident (wave 1)
#define NT 256

typedef unsigned long long u64;

// ---- persistent device state (allocation-free rule) ----
__device__ int g_vcount = 0;
__device__ int g_bar_arrive = 0;
__device__ volatile int g_bar_release = 0;
__device__ int g_bar_exit = 0;
__device__ u64 g_vkey[N];
__device__ float4 g_vbox[N];
__device__ float g_vscore[N];
__device__ int g_rankp[8][N];
__device__ float4 g_sbox[N];
__device__ float g_sscore[N];
__device__ u64 g_mask[N][WORDS];
__device__ u64 g_rnz[N][3];        // per sorted row: bitmap of nonzero mask words

// Software grid barrier (all CTAs co-resident since GRID < #SMs).
__device__ __forceinline__ void gbar(int gen) {
    __syncthreads();
    if (threadIdx.x == 0) {
        __threadfence();
        int prev = atomicAdd(&g_bar_arrive, 1);
        if (prev == gen * GRID - 1) {
            g_bar_release = gen;
        } else {
            while (g_bar_release < gen) { }
        }
        __threadfence();
    }
    __syncthreads();
}

__global__ __launch_bounds__(NT) void k_all(const float* __restrict__ in,
                                            float* __restrict__ out) {
    __shared__ __align__(16) char smraw[8448];   // phase 2/4 scratch
    // reduce-phase scratch (block 0 only)
    __shared__ u64 remv[WORDS];
    __shared__ u64 diag[2][64];
    __shared__ u64 rnzs[2][64][3];
    __shared__ unsigned s_nzlo, s_nzhi;
    int tid = threadIdx.x;
    int bid = blockIdx.x;
    int gtid = bid * NT + tid;

    // ---------------- Phase 1: decode + compact valid ----------------------
    {
        int a = gtid;
        int lane = tid & 31;
        bool valid = false;
        float4 b = make_float4(0.f, 0.f, 0.f, 0.f);
        float s = 0.f;
        u64 key = 0ull;
        if (a < N) {
            float cx = in[a];
            float cy = in[N + a];
            float w  = in[2 * N + a];
            float h  = in[3 * N + a];
            s = in[4 * N + a];
            float hw = __fmul_rn(w, 0.5f);
            float hh = __fmul_rn(h, 0.5f);
            b.x = __fsub_rn(cx, hw);
            b.y = __fsub_rn(cy, hh);
            b.z = __fadd_rn(cx, hw);
            b.w = __fadd_rn(cy, hh);
            valid = (s >= SCORE_THR);
            key = (((u64)__float_as_uint(s)) << 14) | (u64)(16383 - a);
            g_rnz[a][0] = 0ull;     // reset row-nonzero bitmaps for this call
            g_rnz[a][1] = 0ull;
            g_rnz[a][2] = 0ull;
        }
        unsigned m = __ballot_sync(0xffffffffu, valid);
        if (m != 0u) {
            int leader = __ffs(m) - 1;
            int base = 0;
            if (lane == leader) base = atomicAdd(&g_vcount, __popc(m));
            base = __shfl_sync(0xffffffffu, base, leader);
            if (valid) {
                int pos = base + __popc(m & ((1u << lane) - 1u));
                g_vkey[pos]   = key;
                g_vbox[pos]   = b;
                g_vscore[pos] = s;
            }
        }
    }
    gbar(1);
    int V = *(volatile int*)&g_vcount;

    // ---------------- Phase 2: rank partials (i-blocks x 8 j-chunks) -------
    {
        u64* sk = (u64*)smraw;
        int IB = (V + NT - 1) / NT;
        int CH = (V + 7) / 8;
        int ntasks = IB * 8;
        for (int task = bid; task < ntasks; task += GRID) {
            int ib = task % IB;
            int jb = task / IB;
            int jlo = jb * CH;
            int mlen = min(jlo + CH, V) - jlo;
            __syncthreads();
            for (int d = tid; d < mlen; d += NT)
                sk[d] = g_vkey[jlo + d];
            __syncthreads();
            int p = ib * NT + tid;
            u64 kp = (p < V) ? g_vkey[p] : 0ull;
            int cnt = 0;
#pragma unroll 8
            for (int d = 0; d < mlen; ++d)
                cnt += (sk[d] > kp) ? 1 : 0;
            if (p < V) g_rankp[jb][p] = cnt;
        }
    }
    gbar(2);

    // ---------------- Phase 3: sum partials + scatter -----------------------
    for (int p = gtid; p < V; p += GRID * NT) {
        int r = 0;
#pragma unroll
        for (int y = 0; y < 8; ++y) r += g_rankp[y][p];
        g_sbox[r]   = g_vbox[p];
        g_sscore[r] = g_vscore[p];
    }
    gbar(3);

    // ---------------- Phase 4: IoU bitmask + row-nonzero bitmaps -----------
    {
        float4* cbox  = (float4*)smraw;
        float*  carea = (float*)(smraw + 128 * 16);
        int Tv = (V + 127) >> 7;
        int ntasks = Tv * (Tv + 1) / 2;
        for (int task = bid; task < ntasks; task += GRID) {
            int t2 = task, rb = 0;
            while (t2 >= Tv - rb) { t2 -= Tv - rb; rb++; }
            int cb = rb + t2;
            __syncthreads();
            if (tid < 128) {
                int j = cb * 128 + tid;
                if (j < V) {
                    float4 b = g_sbox[j];
                    cbox[tid] = b;
                    carea[tid] = __fmul_rn(__fsub_rn(b.z, b.x),
                                           __fsub_rn(b.w, b.y));
                } else {
                    cbox[tid] = make_float4(0.f, 0.f, 0.f, 0.f);
                    carea[tid] = 0.f;
                }
            }
            __syncthreads();
            int row = tid & 127;
            int half = tid >> 7;
            int i = rb * 128 + row;
            if (i < V) {
                float4 bi = g_sbox[i];
                float ai = __fmul_rn(__fsub_rn(bi.z, bi.x),
                                     __fsub_rn(bi.w, bi.y));
                int cbase = half * 64;
                int wordbase = cb * 128 + cbase;
                int dstart = max(0, i + 1 - wordbase);
                u64 bits = 0ull;
                for (int d = dstart; d < 64; ++d) {
                    float4 bj = cbox[cbase + d];
                    float ltx = fmaxf(bi.x, bj.x);
                    float lty = fmaxf(bi.y, bj.y);
                    float rbx = fminf(bi.z, bj.z);
                    float rby = fminf(bi.w, bj.w);
                    float wx = fmaxf(__fsub_rn(rbx, ltx), 0.0f);
                    float wy = fmaxf(__fsub_rn(rby, lty), 0.0f);
                    float inter = __fmul_rn(wx, wy);
                    float uni = __fsub_rn(__fadd_rn(ai, carea[cbase + d]), inter);
                    float den = fmaxf(uni, 1e-9f);
                    bool hit;
                    if (inter > __fmul_rn(0.5005f, den))      hit = true;
                    else if (inter < __fmul_rn(0.4995f, den)) hit = false;
                    else hit = (__fdiv_rn(inter, den) > IOU_THR);
                    if (hit) bits |= (1ull << d);
                }
                int w = cb * 2 + half;
                g_mask[i][w] = bits;
                if (bits) atomicOr(&g_rnz[i][w >> 6], 1ull << (w & 63));
            }
        }
    }
    gbar(4);

    // ---------------- Phase 5: block 0 — sparse greedy reduce + output -----
    if (bid != 0) {
        __syncthreads();
        if (tid == 0) atomicAdd(&g_bar_exit, 1);
        return;
    }

    int T = (V + 63) >> 6;
    for (int w = tid; w < WORDS; w += NT) remv[w] = 0ull;
    // preload tile 0's diag + rnz
    if (tid < 64) {
        diag[0][tid] = (T > 0 && tid < V) ? g_mask[tid][0] : 0ull;
    } else if (tid < 256) {
        int b = (tid - 64) & 63, k = (tid - 64) >> 6;   // 192 threads, k=0..2
        rnzs[0][b][k] = (T > 0 && b < V) ? g_rnz[b][k] : 0ull;
    }
    __syncthreads();

    for (int t = 0; t < T; ++t) {
        int buf = t & 1;
        // ballot nonzero-diag bitmap (warps 0,1 fully active)
        if (tid < 64) {
            unsigned m = __ballot_sync(0xffffffffu, diag[buf][tid] != 0ull);
            if (tid == 0)  s_nzlo = m;
            if (tid == 32) s_nzhi = m;
        }
        // prefetch tile t+1 (overlaps scan + OR below)
        if (tid < 64) {
            int i = (t + 1) * 64 + tid;
            diag[buf ^ 1][tid] = (t + 1 < T && i < V) ? g_mask[i][t + 1] : 0ull;
        } else if (tid < 256) {
            int b = (tid - 64) & 63, k = (tid - 64) >> 6;
            int i = (t + 1) * 64 + b;
            rnzs[buf ^ 1][b][k] = (t + 1 < T && i < V) ? g_rnz[i][k] : 0ull;
        }
        __syncthreads();
        if (tid == 0) {
            u64 cur = remv[t];
            int rem = V - t * 64;
            if (rem < 64) cur |= (~0ull) << rem;       // rows >= V removed
            u64 nzmask = ((u64)s_nzhi << 32) | (u64)s_nzlo;
            u64 cand = nzmask & ~cur;                  // only bits that can act
            while (cand) {
                int b = __ffsll(cand) - 1;             // kept + nonzero diag
                cur |= diag[buf][b];                   // suppress later bits
                u64 below = (b == 63) ? ~0ull : ((2ull << b) - 1ull);
                cand = nzmask & ~cur & ~below;
            }
            remv[t] = cur;
        }
        __syncthreads();
        // sparse OR: rows kept in this tile push only their nonzero words > t
        if (tid < 192) {
            int b = tid & 63, k = tid >> 6;            // row b, rnz word k
            u64 cur = remv[t];
            int i = t * 64 + b;
            if (!((cur >> b) & 1ull)) {                // row kept
                u64 m = rnzs[buf][b][k];
                int wbase = k << 6;
                if (t >= wbase + 63) m = 0ull;
                else if (t >= wbase) m &= ~((2ull << (t - wbase)) - 1ull);
                while (m) {
                    int w = wbase + __ffsll(m) - 1;
                    m &= m - 1;
                    atomicOr(&remv[w], g_mask[i][w]);
                }
            }
        }
        __syncthreads();
    }

    // output: kept -> [x1,y1,x2,y2,score], else zeros
    for (int p = tid; p < N; p += NT) {
        bool kept = (p < V) && !((remv[p >> 6] >> (p & 63)) & 1ull);
        float4 b = kept ? g_sbox[p] : make_float4(0.f, 0.f, 0.f, 0.f);
        float s = kept ? g_sscore[p] : 0.f;
        out[p * 5 + 0] = b.x;
        out[p * 5 + 1] = b.y;
        out[p * 5 + 2] = b.z;
        out[p * 5 + 3] = b.w;
        out[p * 5 + 4] = s;
    }

    // reset persistent state for the next graph replay
    __syncthreads();
    if (tid == 0) {
        while (*(volatile int*)&g_bar_exit < GRID - 1) { }
        g_bar_exit = 0;
        g_bar_arrive = 0;
        g_bar_release = 0;
        g_vcount = 0;
        __threadfence();
    }
}

extern "C" void kernel_launch(void* const* d_in, const int* in_sizes, int n_in,
                              void* d_out, int out_size) {
    const float* in = (const float*)d_in[0];
    float* out = (float*)d_out;
    k_all<<<GRID, NT>>>(in, out);
}

// round 6
// speedup vs baseline: 2.0634x; 2.0634x over previous
#include <cuda_runtime.h>
#include <cstdint>

#define N 8400
#define WORDS 132          // ceil(8400/64)
#define SCORE_THR 0.5f
#define IOU_THR 0.5f
#define GRID 136           // <= 148 SMs: all blocks co-resident (wave 1)
#define NT 256
#define TW 70              // words cached per row in reduce (fast path: T <= 70)
#define TW16 (TW / 2)      // 16B units per row

typedef unsigned long long u64;

// ---- persistent device state (allocation-free rule) ----
__device__ int g_vcount = 0;
__device__ int g_bar_arrive = 0;
__device__ volatile int g_bar_release = 0;
__device__ int g_bar_exit = 0;
__device__ u64 g_vkey[N];
__device__ float4 g_vbox[N];
__device__ float g_vscore[N];
__device__ int g_rankp[8][N];
__device__ float4 g_sbox[N];
__device__ float g_sscore[N];
__device__ u64 g_mask[N][WORDS];

// Software grid barrier (all CTAs co-resident since GRID < #SMs).
__device__ __forceinline__ void gbar(int gen) {
    __syncthreads();
    if (threadIdx.x == 0) {
        __threadfence();
        int prev = atomicAdd(&g_bar_arrive, 1);
        if (prev == gen * GRID - 1) {
            g_bar_release = gen;
        } else {
            while (g_bar_release < gen) { }
        }
        __threadfence();
    }
    __syncthreads();
}

__device__ __forceinline__ void cpa16(uint32_t saddr, const void* gptr) {
    asm volatile("cp.async.cg.shared.global [%0], [%1], 16;"
                 :: "r"(saddr), "l"(gptr));
}

__global__ __launch_bounds__(NT) void k_all(const float* __restrict__ in,
                                            float* __restrict__ out) {
    extern __shared__ __align__(16) char dyn[];   // 71,680B: phase scratch / reduce buffers
    __shared__ u64 remv[WORDS];
    __shared__ unsigned s_nzlo, s_nzhi;
    int tid = threadIdx.x;
    int bid = blockIdx.x;
    int gtid = bid * NT + tid;

    // ---------------- Phase 1: decode + compact valid ----------------------
    {
        int a = gtid;
        int lane = tid & 31;
        bool valid = false;
        float4 b = make_float4(0.f, 0.f, 0.f, 0.f);
        float s = 0.f;
        u64 key = 0ull;
        if (a < N) {
            float cx = in[a];
            float cy = in[N + a];
            float w  = in[2 * N + a];
            float h  = in[3 * N + a];
            s = in[4 * N + a];
            float hw = __fmul_rn(w, 0.5f);
            float hh = __fmul_rn(h, 0.5f);
            b.x = __fsub_rn(cx, hw);
            b.y = __fsub_rn(cy, hh);
            b.z = __fadd_rn(cx, hw);
            b.w = __fadd_rn(cy, hh);
            valid = (s >= SCORE_THR);
            key = (((u64)__float_as_uint(s)) << 14) | (u64)(16383 - a);
        }
        unsigned m = __ballot_sync(0xffffffffu, valid);
        if (m != 0u) {
            int leader = __ffs(m) - 1;
            int base = 0;
            if (lane == leader) base = atomicAdd(&g_vcount, __popc(m));
            base = __shfl_sync(0xffffffffu, base, leader);
            if (valid) {
                int pos = base + __popc(m & ((1u << lane) - 1u));
                g_vkey[pos]   = key;
                g_vbox[pos]   = b;
                g_vscore[pos] = s;
            }
        }
    }
    gbar(1);
    int V = *(volatile int*)&g_vcount;

    // ---------------- Phase 2: rank partials (i-blocks x 8 j-chunks) -------
    {
        u64* sk = (u64*)dyn;
        int IB = (V + NT - 1) / NT;
        int CH = (V + 7) / 8;
        int ntasks = IB * 8;
        for (int task = bid; task < ntasks; task += GRID) {
            int ib = task % IB;
            int jb = task / IB;
            int jlo = jb * CH;
            int mlen = min(jlo + CH, V) - jlo;
            __syncthreads();
            for (int d = tid; d < mlen; d += NT)
                sk[d] = g_vkey[jlo + d];
            __syncthreads();
            int p = ib * NT + tid;
            u64 kp = (p < V) ? g_vkey[p] : 0ull;
            int cnt = 0;
#pragma unroll 8
            for (int d = 0; d < mlen; ++d)
                cnt += (sk[d] > kp) ? 1 : 0;
            if (p < V) g_rankp[jb][p] = cnt;
        }
    }
    gbar(2);

    // ---------------- Phase 3: sum partials + scatter -----------------------
    for (int p = gtid; p < V; p += GRID * NT) {
        int r = 0;
#pragma unroll
        for (int y = 0; y < 8; ++y) r += g_rankp[y][p];
        g_sbox[r]   = g_vbox[p];
        g_sscore[r] = g_vscore[p];
    }
    gbar(3);

    // ---------------- Phase 4: IoU bitmask (128x128 triangle tiles) --------
    {
        float4* cbox  = (float4*)dyn;
        float*  carea = (float*)(dyn + 128 * 16);
        int Tv = (V + 127) >> 7;
        int ntasks = Tv * (Tv + 1) / 2;
        for (int task = bid; task < ntasks; task += GRID) {
            int t2 = task, rb = 0;
            while (t2 >= Tv - rb) { t2 -= Tv - rb; rb++; }
            int cb = rb + t2;
            __syncthreads();
            if (tid < 128) {
                int j = cb * 128 + tid;
                if (j < V) {
                    float4 b = g_sbox[j];
                    cbox[tid] = b;
                    carea[tid] = __fmul_rn(__fsub_rn(b.z, b.x),
                                           __fsub_rn(b.w, b.y));
                } else {
                    cbox[tid] = make_float4(0.f, 0.f, 0.f, 0.f);
                    carea[tid] = 0.f;
                }
            }
            __syncthreads();
            int row = tid & 127;
            int half = tid >> 7;
            int i = rb * 128 + row;
            if (i < V) {
                float4 bi = g_sbox[i];
                float ai = __fmul_rn(__fsub_rn(bi.z, bi.x),
                                     __fsub_rn(bi.w, bi.y));
                int cbase = half * 64;
                int wordbase = cb * 128 + cbase;
                int dstart = max(0, i + 1 - wordbase);
                u64 bits = 0ull;
                for (int d = dstart; d < 64; ++d) {
                    float4 bj = cbox[cbase + d];
                    float ltx = fmaxf(bi.x, bj.x);
                    float lty = fmaxf(bi.y, bj.y);
                    float rbx = fminf(bi.z, bj.z);
                    float rby = fminf(bi.w, bj.w);
                    float wx = fmaxf(__fsub_rn(rbx, ltx), 0.0f);
                    float wy = fmaxf(__fsub_rn(rby, lty), 0.0f);
                    float inter = __fmul_rn(wx, wy);
                    float uni = __fsub_rn(__fadd_rn(ai, carea[cbase + d]), inter);
                    float den = fmaxf(uni, 1e-9f);
                    bool hit;
                    if (inter > __fmul_rn(0.5005f, den))      hit = true;
                    else if (inter < __fmul_rn(0.4995f, den)) hit = false;
                    else hit = (__fdiv_rn(inter, den) > IOU_THR);
                    if (hit) bits |= (1ull << d);
                }
                g_mask[i][cb * 2 + half] = bits;
            }
        }
    }
    gbar(4);

    // ---------------- Phase 5: block 0 — staged greedy reduce + output -----
    if (bid != 0) {
        __syncthreads();
        if (tid == 0) atomicAdd(&g_bar_exit, 1);
        return;
    }

    int T = (V + 63) >> 6;
    __syncthreads();
    for (int w = tid; w < WORDS; w += NT) remv[w] = 0ull;

    if (T > 0 && T <= TW) {
        // Fast path: double-buffered SMEM staging of whole tiles via cp.async
        u64 (*buf)[64][TW] = (u64 (*)[64][TW])dyn;   // 2 x 64 x 70 x 8B
        // stage tile 0
        for (int u = tid; u < 64 * TW16; u += NT) {
            int r = u / TW16, c = u % TW16;
            int i = min(r, N - 1);
            cpa16((uint32_t)__cvta_generic_to_shared(&buf[0][r][c * 2]),
                  &g_mask[i][c * 2]);
        }
        asm volatile("cp.async.commit_group;");

        for (int t = 0; t < T; ++t) {
            int cur = t & 1;
            asm volatile("cp.async.wait_group 0;" ::: "memory");
            __syncthreads();                      // buf[cur] visible to all
            if (t + 1 < T) {                      // stage next tile (overlapped)
                int ibase = (t + 1) * 64;
                for (int u = tid; u < 64 * TW16; u += NT) {
                    int r = u / TW16, c = u % TW16;
                    int i = min(ibase + r, N - 1);
                    cpa16((uint32_t)__cvta_generic_to_shared(&buf[cur ^ 1][r][c * 2]),
                          &g_mask[i][c * 2]);
                }
                asm volatile("cp.async.commit_group;");
            }
            if (tid < 64) {                       // nonzero-diag bitmap
                unsigned m = __ballot_sync(0xffffffffu, buf[cur][tid][t] != 0ull);
                if (tid == 0)  s_nzlo = m;
                if (tid == 32) s_nzhi = m;
            }
            __syncthreads();
            if (tid == 0) {                       // serial intra-tile scan (SMEM only)
                u64 c = remv[t];
                int rem = V - t * 64;
                if (rem < 64) c |= (~0ull) << rem;
                u64 nz = ((u64)s_nzhi << 32) | (u64)s_nzlo;
                u64 cand = nz & ~c;               // kept bits with nonzero diag
                while (cand) {
                    int b = __ffsll(cand) - 1;
                    c |= buf[cur][b][t];
                    u64 below = (b == 63) ? ~0ull : ((2ull << b) - 1ull);
                    cand = nz & ~c & ~below;
                }
                remv[t] = c;
            }
            __syncthreads();
            // parallel OR: thread owns word w, loops kept rows via ffs (SMEM only)
            u64 keep = ~remv[t];                  // rows >= V already marked removed
            for (int w = t + 1 + tid; w < T; w += NT) {
                u64 acc = remv[w];
                u64 kk = keep;
                while (kk) {
                    int b = __ffsll(kk) - 1;
                    kk &= kk - 1;
                    acc |= buf[cur][b][w];
                }
                remv[w] = acc;
            }
            __syncthreads();
        }
    } else if (T > 0) {
        // Fallback (T > TW): direct-global version, correctness only
        __shared__ u64 fdiag[64];
        for (int t = 0; t < T; ++t) {
            if (tid < 64) {
                int i = t * 64 + tid;
                fdiag[tid] = (i < V) ? g_mask[i][t] : 0ull;
            }
            __syncthreads();
            if (tid == 0) {
                u64 c = remv[t];
                int rem = V - t * 64;
                if (rem < 64) c |= (~0ull) << rem;
                u64 expl = c;
                while (~expl) {
                    int b = __ffsll(~expl) - 1;
                    c |= fdiag[b];
                    expl = c | ((b == 63) ? ~0ull : ((2ull << b) - 1ull));
                }
                remv[t] = c;
            }
            __syncthreads();
            u64 keep = ~remv[t];
            for (int w = t + 1 + tid; w < T; w += NT) {
                u64 acc = remv[w];
                u64 kk = keep;
                while (kk) {
                    int b = __ffsll(kk) - 1;
                    kk &= kk - 1;
                    acc |= g_mask[t * 64 + b][w];
                }
                remv[w] = acc;
            }
            __syncthreads();
        }
    }

    // output: kept -> [x1,y1,x2,y2,score], else zeros
    for (int p = tid; p < N; p += NT) {
        bool kept = (p < V) && !((remv[p >> 6] >> (p & 63)) & 1ull);
        float4 b = kept ? g_sbox[p] : make_float4(0.f, 0.f, 0.f, 0.f);
        float s = kept ? g_sscore[p] : 0.f;
        out[p * 5 + 0] = b.x;
        out[p * 5 + 1] = b.y;
        out[p * 5 + 2] = b.z;
        out[p * 5 + 3] = b.w;
        out[p * 5 + 4] = s;
    }

    // reset persistent state for the next graph replay
    __syncthreads();
    if (tid == 0) {
        while (*(volatile int*)&g_bar_exit < GRID - 1) { }
        g_bar_exit = 0;
        g_bar_arrive = 0;
        g_bar_release = 0;
        g_vcount = 0;
        __threadfence();
    }
}

extern "C" void kernel_launch(void* const* d_in, const int* in_sizes, int n_in,
                              void* d_out, int out_size) {
    const float* in = (const float*)d_in[0];
    float* out = (float*)d_out;
    static_assert(2 * 64 * TW * 8 == 71680, "buffer size");
    cudaFuncSetAttribute(k_all, cudaFuncAttributeMaxDynamicSharedMemorySize, 71680);
    k_all<<<GRID, NT, 71680>>>(in, out);
}